// round 3
// baseline (speedup 1.0000x reference)
#include <cuda_runtime.h>
#include <cstdint>

// ---------------------------------------------------------------------------
// Problem constants
//   feat0_c, feat1_c : [2,128,32,32] fp32
//   feat0_f, feat1_f : [2,128,64,64] fp32
// Outputs (concatenated fp32): see offsets below.
// ---------------------------------------------------------------------------

static const size_t OFF_TF    = 0;
static const size_t OFF_TFC   = 2097152;
static const size_t OFF_C     = 4194304;
static const size_t OFF_CF    = 37748736;
static const size_t OFF_FLOW  = 71303168;
static const size_t OFF_FLOWF = 71319552;

// Scratch (device globals — no allocation allowed)
__device__ float g_cc[2 * 1024 * 1024];          // corr_c  [b][p0c][p1c]   8 MB
__device__ float g_i1[2 * 1024 * 4096];          // (u,v)-upsampled corr_c  33.5 MB (L2-resident)

// ---------------------------------------------------------------------------
// helpers
// ---------------------------------------------------------------------------
__device__ __forceinline__ float to_tf32(float x) {
    uint32_t u;
    asm("cvt.rna.tf32.f32 %0, %1;" : "=r"(u) : "f"(x));
    return __uint_as_float(u);
}

__device__ __forceinline__ void mma_tf32(float* d, const uint32_t* a, const uint32_t* b) {
    asm volatile(
        "mma.sync.aligned.m16n8k8.row.col.f32.tf32.tf32.f32 "
        "{%0,%1,%2,%3}, {%4,%5,%6,%7}, {%8,%9}, {%0,%1,%2,%3};\n"
        : "+f"(d[0]), "+f"(d[1]), "+f"(d[2]), "+f"(d[3])
        : "r"(a[0]), "r"(a[1]), "r"(a[2]), "r"(a[3]), "r"(b[0]), "r"(b[1]));
}

__device__ __forceinline__ void lerp_weights(int i, int& i0, int& i1, float& w) {
    float f = (float)(i * 31) / 63.0f;   // align_corners scale 31/63, exact at i=0,63
    i0 = (int)f;
    w  = f - (float)i0;
    i1 = min(i0 + 1, 31);
}

// ---------------------------------------------------------------------------
// Correlation GEMM (tf32x3, fp32-accurate):
//   C[m,n] = sum_k f0[b,k,m] * f1[b,k,n] * (1/sqrt(128))
// MT = M = N (1024 coarse, 4096 fine). Block tile 128x128, BK=16, 8 warps.
// FUSE epilogue: c = 0.5*(rowinterp(g_i1) + corr), writes c + c_flip.
// Row-interp is done per block: y-blend of g_i1 rows into smem Y, then
// x-blend per output element (g_i1 is L2-resident; no 134MB scratch volume).
// Dynamic smem: mainloop 8704 floats; epilogue union S(128x65)+Y(64x68).
// ---------------------------------------------------------------------------
template <int MT, bool FUSE>
__global__ __launch_bounds__(256)
void gemm_corr_kernel(const float* __restrict__ f0, const float* __restrict__ f1,
                      float* __restrict__ outC, float* __restrict__ outF)
{
    extern __shared__ float smem[];
    float* AsH = smem;
    float* AsL = smem + 2176;
    float* BsH = smem + 4352;
    float* BsL = smem + 6528;

    const int b  = blockIdx.z;
    const int m0 = blockIdx.y * 128;
    const int n0 = blockIdx.x * 128;
    const float* A  = f0 + (size_t)b * 128 * MT;  // [K=128][MT]
    const float* Bg = f1 + (size_t)b * 128 * MT;

    const int tid  = threadIdx.x;
    const int warp = tid >> 5, lane = tid & 31;
    const int gid  = lane >> 2, tig = lane & 3;
    const int wm0  = (warp >> 1) * 32;           // warp m-offset (4 warps)
    const int wn0  = (warp & 1) * 64;            // warp n-offset (2 warps)

    float acc[2][8][4];
#pragma unroll
    for (int mi = 0; mi < 2; mi++)
#pragma unroll
        for (int j = 0; j < 8; j++)
#pragma unroll
            for (int r = 0; r < 4; r++) acc[mi][j][r] = 0.0f;

    for (int k0 = 0; k0 < 128; k0 += 16) {
#pragma unroll
        for (int q = 0; q < 2; q++) {
            int idx = tid + q * 256;             // float4 index within 16x128 tile
            int kk  = idx >> 5;
            int mf  = (idx & 31) << 2;
            float4 va = *reinterpret_cast<const float4*>(A  + (size_t)(k0 + kk) * MT + m0 + mf);
            float4 vb = *reinterpret_cast<const float4*>(Bg + (size_t)(k0 + kk) * MT + n0 + mf);
            float4 ah = make_float4(to_tf32(va.x), to_tf32(va.y), to_tf32(va.z), to_tf32(va.w));
            float4 bh = make_float4(to_tf32(vb.x), to_tf32(vb.y), to_tf32(vb.z), to_tf32(vb.w));
            float4 al = make_float4(to_tf32(va.x - ah.x), to_tf32(va.y - ah.y),
                                    to_tf32(va.z - ah.z), to_tf32(va.w - ah.w));
            float4 bl = make_float4(to_tf32(vb.x - bh.x), to_tf32(vb.y - bh.y),
                                    to_tf32(vb.z - bh.z), to_tf32(vb.w - bh.w));
            *reinterpret_cast<float4*>(&AsH[kk * 136 + mf]) = ah;
            *reinterpret_cast<float4*>(&AsL[kk * 136 + mf]) = al;
            *reinterpret_cast<float4*>(&BsH[kk * 136 + mf]) = bh;
            *reinterpret_cast<float4*>(&BsL[kk * 136 + mf]) = bl;
        }
        __syncthreads();

#pragma unroll
        for (int ks = 0; ks < 2; ks++) {
            const int r0 = (ks * 8 + tig) * 136;
            const int r1 = (ks * 8 + tig + 4) * 136;
            uint32_t afh[2][4], afl[2][4], bfh[8][2], bfl[8][2];
#pragma unroll
            for (int mi = 0; mi < 2; mi++) {
                int mc = wm0 + mi * 16 + gid;
                afh[mi][0] = __float_as_uint(AsH[r0 + mc]);
                afh[mi][1] = __float_as_uint(AsH[r0 + mc + 8]);
                afh[mi][2] = __float_as_uint(AsH[r1 + mc]);
                afh[mi][3] = __float_as_uint(AsH[r1 + mc + 8]);
                afl[mi][0] = __float_as_uint(AsL[r0 + mc]);
                afl[mi][1] = __float_as_uint(AsL[r0 + mc + 8]);
                afl[mi][2] = __float_as_uint(AsL[r1 + mc]);
                afl[mi][3] = __float_as_uint(AsL[r1 + mc + 8]);
            }
#pragma unroll
            for (int j = 0; j < 8; j++) {
                int nc = wn0 + j * 8 + gid;
                bfh[j][0] = __float_as_uint(BsH[r0 + nc]);
                bfh[j][1] = __float_as_uint(BsH[r1 + nc]);
                bfl[j][0] = __float_as_uint(BsL[r0 + nc]);
                bfl[j][1] = __float_as_uint(BsL[r1 + nc]);
            }
#pragma unroll
            for (int mi = 0; mi < 2; mi++)
#pragma unroll
                for (int j = 0; j < 8; j++) {
                    mma_tf32(acc[mi][j], afl[mi], bfh[j]);   // lo*hi
                    mma_tf32(acc[mi][j], afh[mi], bfl[j]);   // hi*lo
                    mma_tf32(acc[mi][j], afh[mi], bfh[j]);   // hi*hi
                }
        }
        __syncthreads();
    }

    const float sc = 0.08838834764831845f;       // 1/sqrt(128)

    if constexpr (!FUSE) {
        // coarse: write scaled correlation to g_cc
        float* out = g_cc + (size_t)b * MT * MT;
        (void)outC; (void)outF;
#pragma unroll
        for (int mi = 0; mi < 2; mi++)
#pragma unroll
            for (int j = 0; j < 8; j++) {
                int r0 = m0 + wm0 + mi * 16 + gid;
                int cc = n0 + wn0 + j * 8 + 2 * tig;
                float2 v0 = make_float2(acc[mi][j][0] * sc, acc[mi][j][1] * sc);
                float2 v1 = make_float2(acc[mi][j][2] * sc, acc[mi][j][3] * sc);
                *reinterpret_cast<float2*>(&out[(size_t)r0 * MT + cc])       = v0;
                *reinterpret_cast<float2*>(&out[(size_t)(r0 + 8) * MT + cc]) = v1;
            }
    } else {
        // fine: c = 0.5*(rowinterp + corr), plus transposed write for c_flip
        float* S = smem;                          // 128 x 65 (33.3 KB)
        float* Y = smem + 8320;                   // 64 x 68  (17.4 KB): y-blended g_i1
        const size_t cb = (size_t)b * MT * MT;
        const int h0base = m0 >> 6;               // two h0 values: h0base, h0base+1

#pragma unroll
        for (int ch = 0; ch < 2; ch++) {
            const int nbase = n0 + ch * 64;

            // --- store this half's corr into S ---
            if ((warp & 1) == ch) {
#pragma unroll
                for (int mi = 0; mi < 2; mi++)
#pragma unroll
                    for (int j = 0; j < 8; j++) {
                        int r0  = wm0 + mi * 16 + gid;
                        int col = j * 8 + 2 * tig;
                        S[r0 * 65 + col]           = acc[mi][j][0] * sc;
                        S[r0 * 65 + col + 1]       = acc[mi][j][1] * sc;
                        S[(r0 + 8) * 65 + col]     = acc[mi][j][2] * sc;
                        S[(r0 + 8) * 65 + col + 1] = acc[mi][j][3] * sc;
                    }
            }

            // --- build Y: y-blend of g_i1 rows for the 2 h0 values, 32 cx, 64 cols ---
            // 1024 float4 elements: e -> h0loc (1b), cx (5b), c4 (4b)
#pragma unroll
            for (int t = 0; t < 4; t++) {
                int e     = tid + t * 256;
                int h0loc = e >> 9;
                int cx    = (e >> 4) & 31;
                int c4    = e & 15;
                int y0, y1; float wy;
                lerp_weights(h0base + h0loc, y0, y1, wy);
                const float4* p0 = reinterpret_cast<const float4*>(
                    g_i1 + ((size_t)b * 1024 + y0 * 32 + cx) * 4096 + nbase) + c4;
                const float4* p1 = reinterpret_cast<const float4*>(
                    g_i1 + ((size_t)b * 1024 + y1 * 32 + cx) * 4096 + nbase) + c4;
                float4 a = *p0, bb = *p1;
                float4 v;
                v.x = a.x + wy * (bb.x - a.x);
                v.y = a.y + wy * (bb.y - a.y);
                v.z = a.z + wy * (bb.z - a.z);
                v.w = a.w + wy * (bb.w - a.w);
                *reinterpret_cast<float4*>(&Y[(h0loc * 32 + cx) * 68 + c4 * 4]) = v;
            }
            __syncthreads();

            // --- combine: x-blend + corr, write c, keep combined in S ---
#pragma unroll
            for (int q = 0; q < 8; q++) {
                int idx = tid + q * 256;          // float4 units over 128x64
                int r   = idx >> 4;
                int cf  = (idx & 15) << 2;
                int h0loc = r >> 6;
                int w0    = r & 63;
                int x0, x1; float wx;
                lerp_weights(w0, x0, x1, wx);
                float4 ya = *reinterpret_cast<const float4*>(&Y[(h0loc * 32 + x0) * 68 + cf]);
                float4 yb = *reinterpret_cast<const float4*>(&Y[(h0loc * 32 + x1) * 68 + cf]);
                float4 ip;
                ip.x = ya.x + wx * (yb.x - ya.x);
                ip.y = ya.y + wx * (yb.y - ya.y);
                ip.z = ya.z + wx * (yb.z - ya.z);
                ip.w = ya.w + wx * (yb.w - ya.w);
                size_t ga = cb + (size_t)(m0 + r) * MT + nbase + cf;
                float4 v;
                v.x = 0.5f * (ip.x + S[r * 65 + cf]);
                v.y = 0.5f * (ip.y + S[r * 65 + cf + 1]);
                v.z = 0.5f * (ip.z + S[r * 65 + cf + 2]);
                v.w = 0.5f * (ip.w + S[r * 65 + cf + 3]);
                *reinterpret_cast<float4*>(outC + ga) = v;
                S[r * 65 + cf]     = v.x;         // keep combined value for flip write
                S[r * 65 + cf + 1] = v.y;
                S[r * 65 + cf + 2] = v.z;
                S[r * 65 + cf + 3] = v.w;
            }
            __syncthreads();

            // --- transposed rows: c_flip[n][m0..m0+127] ---
#pragma unroll
            for (int jr = 0; jr < 8; jr++) {
                int n = warp * 8 + jr;
                size_t fb = cb + (size_t)(nbase + n) * MT + m0;
#pragma unroll
                for (int q = 0; q < 4; q++) {
                    int m = lane + q * 32;        // bank = (m+n)%32 -> conflict-free
                    outF[fb + m] = S[m * 65 + n];
                }
            }
            __syncthreads();
        }
    }
}

// ---------------------------------------------------------------------------
// trans_features_coarse: bilinear 32->64 (align_corners) per channel
// ---------------------------------------------------------------------------
__global__ __launch_bounds__(256)
void resize_coarse_kernel(const float* __restrict__ a, const float* __restrict__ bsrc,
                          float* __restrict__ out)
{
    __shared__ float s[1024];
    int blk = blockIdx.x;                        // 0..511
    int bb = blk >> 8, ii = (blk >> 7) & 1, ch = blk & 127;
    const float* in = (ii ? bsrc : a) + ((size_t)bb * 128 + ch) * 1024;
    float* o = out + (((size_t)bb * 2 + ii) * 128 + ch) * 4096;
    int tid = threadIdx.x;
#pragma unroll
    for (int q = 0; q < 4; q++) s[tid + q * 256] = in[tid + q * 256];
    __syncthreads();
#pragma unroll
    for (int q = 0; q < 16; q++) {
        int oi = tid + q * 256;
        int oy = oi >> 6, ox = oi & 63;
        int y0, y1, x0, x1; float wy, wx;
        lerp_weights(oy, y0, y1, wy);
        lerp_weights(ox, x0, x1, wx);
        float v = (1.0f - wy) * ((1.0f - wx) * s[y0 * 32 + x0] + wx * s[y0 * 32 + x1])
                +         wy  * ((1.0f - wx) * s[y1 * 32 + x0] + wx * s[y1 * 32 + x1]);
        o[oi] = v;
    }
}

// ---------------------------------------------------------------------------
// interp pass A: per (b,p0c) row, upsample (u,v) 32x32 -> 64x64
// ---------------------------------------------------------------------------
__global__ __launch_bounds__(256)
void interpA_kernel()
{
    __shared__ float s[1024];
    int blk = blockIdx.x;                        // 0..2047 = b*1024 + p0c
    const float* in = g_cc + (size_t)blk * 1024;
    float* o = g_i1 + (size_t)blk * 4096;
    int tid = threadIdx.x;
#pragma unroll
    for (int q = 0; q < 4; q++) s[tid + q * 256] = in[tid + q * 256];
    __syncthreads();
#pragma unroll
    for (int q = 0; q < 16; q++) {
        int oi = tid + q * 256;
        int oy = oi >> 6, ox = oi & 63;
        int y0, y1, x0, x1; float wy, wx;
        lerp_weights(oy, y0, y1, wy);
        lerp_weights(ox, x0, x1, wx);
        float v = (1.0f - wy) * ((1.0f - wx) * s[y0 * 32 + x0] + wx * s[y0 * 32 + x1])
                +         wy  * ((1.0f - wx) * s[y1 * 32 + x0] + wx * s[y1 * 32 + x1]);
        o[oi] = v;
    }
}

// ---------------------------------------------------------------------------
// soft-argmax: softmax(row/0.02) over 4096 source positions, marginal means.
// One block per (target pixel, batch); z selects (c -> flow) / (c_flip -> flow_flip).
// ---------------------------------------------------------------------------
__global__ __launch_bounds__(256)
void softargmax_kernel(const float* __restrict__ c0, const float* __restrict__ c1,
                       float* __restrict__ fl0, float* __restrict__ fl1)
{
    const int t  = blockIdx.x;
    const int bb = blockIdx.y;
    const float* cmat = blockIdx.z ? c1 : c0;
    float* flow       = blockIdx.z ? fl1 : fl0;
    const float* row = cmat + ((size_t)bb * 4096 + t) * 4096;
    const int tid = threadIdx.x;
    const int warp = tid >> 5, lane = tid & 31;

    float v[16];
    const float4* r4 = reinterpret_cast<const float4*>(row) + tid * 4;
#pragma unroll
    for (int q = 0; q < 4; q++) {
        float4 x = r4[q];
        v[q * 4] = x.x; v[q * 4 + 1] = x.y; v[q * 4 + 2] = x.z; v[q * 4 + 3] = x.w;
    }

    float mx = v[0];
#pragma unroll
    for (int e = 1; e < 16; e++) mx = fmaxf(mx, v[e]);
#pragma unroll
    for (int o = 16; o; o >>= 1) mx = fmaxf(mx, __shfl_xor_sync(0xffffffffu, mx, o));

    __shared__ float smax[8];
    if (lane == 0) smax[warp] = mx;
    __syncthreads();
    mx = smax[0];
#pragma unroll
    for (int i = 1; i < 8; i++) mx = fmaxf(mx, smax[i]);

    float Z = 0.0f, Sx = 0.0f, Sy = 0.0f;
    const int base = tid * 16;
#pragma unroll
    for (int e = 0; e < 16; e++) {
        float tt = (v[e] - mx) * 50.0f;           // /beta = *50
        if (tt > -25.0f) {                        // skipped terms < 1.4e-11 * Z
            float ee = __expf(tt);
            int idx = base + e;
            float xn = (float)((idx & 63) * 2) / 63.0f - 1.0f;
            float yn = (float)((idx >> 6) * 2) / 63.0f - 1.0f;
            Z += ee; Sx += ee * xn; Sy += ee * yn;
        }
    }
#pragma unroll
    for (int o = 16; o; o >>= 1) {
        Z  += __shfl_xor_sync(0xffffffffu, Z,  o);
        Sx += __shfl_xor_sync(0xffffffffu, Sx, o);
        Sy += __shfl_xor_sync(0xffffffffu, Sy, o);
    }
    __shared__ float sz[8], sxs[8], sys[8];
    if (lane == 0) { sz[warp] = Z; sxs[warp] = Sx; sys[warp] = Sy; }
    __syncthreads();
    if (tid == 0) {
        float z = 0.0f, X = 0.0f, Y = 0.0f;
#pragma unroll
        for (int i = 0; i < 8; i++) { z += sz[i]; X += sxs[i]; Y += sys[i]; }
        float gx = X / z, gy = Y / z;
        float w = (float)(t & 63), h = (float)(t >> 6);
        flow[(size_t)bb * 2 * 4096 + t]        = (gx + 1.0f) * 31.5f - w;
        flow[(size_t)bb * 2 * 4096 + 4096 + t] = (gy + 1.0f) * 31.5f - h;
    }
}

// ---------------------------------------------------------------------------
// launch
// ---------------------------------------------------------------------------
extern "C" void kernel_launch(void* const* d_in, const int* in_sizes, int n_in,
                              void* d_out, int out_size)
{
    (void)in_sizes; (void)n_in; (void)out_size;
    const float* f0c = (const float*)d_in[0];
    const float* f1c = (const float*)d_in[1];
    const float* f0f = (const float*)d_in[2];
    const float* f1f = (const float*)d_in[3];
    float* out = (float*)d_out;

    static bool attr_done = false;
    if (!attr_done) {
        cudaFuncSetAttribute(gemm_corr_kernel<4096, true>,
                             cudaFuncAttributeMaxDynamicSharedMemorySize, 50688);
        attr_done = true;
    }

    // trans_features = stack([feat0_f, feat1_f], axis=1): [b][i][C*64*64]
    const size_t chunk = (size_t)128 * 4096;      // floats per (b,i)
    cudaMemcpyAsync(out + OFF_TF + 0 * chunk, f0f,         chunk * 4, cudaMemcpyDeviceToDevice, 0);
    cudaMemcpyAsync(out + OFF_TF + 1 * chunk, f1f,         chunk * 4, cudaMemcpyDeviceToDevice, 0);
    cudaMemcpyAsync(out + OFF_TF + 2 * chunk, f0f + chunk, chunk * 4, cudaMemcpyDeviceToDevice, 0);
    cudaMemcpyAsync(out + OFF_TF + 3 * chunk, f1f + chunk, chunk * 4, cudaMemcpyDeviceToDevice, 0);

    resize_coarse_kernel<<<512, 256>>>(f0c, f1c, out + OFF_TFC);

    gemm_corr_kernel<1024, false><<<dim3(8, 8, 2), 256, 34816>>>(f0c, f1c, nullptr, nullptr);
    interpA_kernel<<<2048, 256>>>();
    gemm_corr_kernel<4096, true><<<dim3(32, 32, 2), 256, 50688>>>(f0f, f1f, out + OFF_C, out + OFF_CF);

    softargmax_kernel<<<dim3(4096, 2, 2), 256>>>(out + OFF_C, out + OFF_CF,
                                                 out + OFF_FLOW, out + OFF_FLOWF);
}

// round 4
// speedup vs baseline: 1.1225x; 1.1225x over previous
#include <cuda_runtime.h>
#include <cstdint>

// ---------------------------------------------------------------------------
// Problem constants
//   feat0_c, feat1_c : [2,128,32,32] fp32
//   feat0_f, feat1_f : [2,128,64,64] fp32
// ---------------------------------------------------------------------------

static const size_t OFF_TF    = 0;
static const size_t OFF_TFC   = 2097152;
static const size_t OFF_C     = 4194304;
static const size_t OFF_CF    = 37748736;
static const size_t OFF_FLOW  = 71303168;
static const size_t OFF_FLOWF = 71319552;

// Scratch (device globals — no allocation allowed)
__device__ float g_cc[2 * 1024 * 1024];          // corr_c  [b][p0c][p1c]   8 MB
__device__ float g_i1[2 * 1024 * 4096];          // (u,v)-upsampled corr_c  33.5 MB (L2-resident)

// ---------------------------------------------------------------------------
// helpers
// ---------------------------------------------------------------------------
__device__ __forceinline__ float to_tf32(float x) {
    uint32_t u;
    asm("cvt.rna.tf32.f32 %0, %1;" : "=r"(u) : "f"(x));
    return __uint_as_float(u);
}

__device__ __forceinline__ void mma_tf32(float* d, const uint32_t* a, const uint32_t* b) {
    asm volatile(
        "mma.sync.aligned.m16n8k8.row.col.f32.tf32.tf32.f32 "
        "{%0,%1,%2,%3}, {%4,%5,%6,%7}, {%8,%9}, {%0,%1,%2,%3};\n"
        : "+f"(d[0]), "+f"(d[1]), "+f"(d[2]), "+f"(d[3])
        : "r"(a[0]), "r"(a[1]), "r"(a[2]), "r"(a[3]), "r"(b[0]), "r"(b[1]));
}

__device__ __forceinline__ void lerp_weights(int i, int& i0, int& i1, float& w) {
    float f = (float)(i * 31) / 63.0f;   // align_corners scale 31/63, exact at i=0,63
    i0 = (int)f;
    w  = f - (float)i0;
    i1 = min(i0 + 1, 31);
}

// ---------------------------------------------------------------------------
// Correlation GEMM (tf32x3, fp32-accurate), 512 threads / 16 warps:
//   C[m,n] = sum_k f0[b,k,m] * f1[b,k,n] * (1/sqrt(128))
// Block tile 128x128, warp tile 32x32 (4x4 warp grid), BK=16.
// Register-prefetch pipeline: next k-block's global loads issued before
// computing the current smem stage; hi/lo tf32 split done at smem store.
// FUSE epilogue: c = 0.5*(rowinterp(g_i1) + corr), writes c + c_flip.
// ---------------------------------------------------------------------------
template <int MT, bool FUSE>
__global__ __launch_bounds__(512)
void gemm_corr_kernel(const float* __restrict__ f0, const float* __restrict__ f1,
                      float* __restrict__ outC, float* __restrict__ outF)
{
    extern __shared__ float smem[];
    float* AsH = smem;                   // 16 x 136
    float* AsL = smem + 2176;
    float* BsH = smem + 4352;
    float* BsL = smem + 6528;

    const int b  = blockIdx.z;
    const int m0 = blockIdx.y * 128;
    const int n0 = blockIdx.x * 128;
    const float* A  = f0 + (size_t)b * 128 * MT;  // [K=128][MT]
    const float* Bg = f1 + (size_t)b * 128 * MT;

    const int tid  = threadIdx.x;
    const int warp = tid >> 5, lane = tid & 31;
    const int gid  = lane >> 2, tig = lane & 3;
    const int wm0  = (warp >> 2) * 32;           // 4 warp rows
    const int wn0  = (warp & 3) * 32;            // 4 warp cols

    float acc[2][4][4];
#pragma unroll
    for (int mi = 0; mi < 2; mi++)
#pragma unroll
        for (int j = 0; j < 4; j++)
#pragma unroll
            for (int r = 0; r < 4; r++) acc[mi][j][r] = 0.0f;

    // loader: one float4 per thread per tile per k-block (16x128 tile)
    const int lkk = tid >> 5;            // 0..15
    const int lmf = (tid & 31) << 2;

    float4 pa = *reinterpret_cast<const float4*>(A  + (size_t)lkk * MT + m0 + lmf);
    float4 pb = *reinterpret_cast<const float4*>(Bg + (size_t)lkk * MT + n0 + lmf);

#define STORE_TILES()                                                              \
    do {                                                                           \
        float4 ah = make_float4(to_tf32(pa.x), to_tf32(pa.y), to_tf32(pa.z), to_tf32(pa.w)); \
        float4 bh = make_float4(to_tf32(pb.x), to_tf32(pb.y), to_tf32(pb.z), to_tf32(pb.w)); \
        float4 al = make_float4(to_tf32(pa.x - ah.x), to_tf32(pa.y - ah.y),        \
                                to_tf32(pa.z - ah.z), to_tf32(pa.w - ah.w));       \
        float4 bl = make_float4(to_tf32(pb.x - bh.x), to_tf32(pb.y - bh.y),        \
                                to_tf32(pb.z - bh.z), to_tf32(pb.w - bh.w));       \
        *reinterpret_cast<float4*>(&AsH[lkk * 136 + lmf]) = ah;                    \
        *reinterpret_cast<float4*>(&AsL[lkk * 136 + lmf]) = al;                    \
        *reinterpret_cast<float4*>(&BsH[lkk * 136 + lmf]) = bh;                    \
        *reinterpret_cast<float4*>(&BsL[lkk * 136 + lmf]) = bl;                    \
    } while (0)

    STORE_TILES();
    __syncthreads();

    for (int kb = 0; kb < 8; kb++) {
        if (kb < 7) {                     // prefetch next k-block (hidden behind MMA)
            pa = *reinterpret_cast<const float4*>(A  + (size_t)((kb + 1) * 16 + lkk) * MT + m0 + lmf);
            pb = *reinterpret_cast<const float4*>(Bg + (size_t)((kb + 1) * 16 + lkk) * MT + n0 + lmf);
        }
#pragma unroll
        for (int ks = 0; ks < 2; ks++) {
            const int r0 = (ks * 8 + tig) * 136;
            const int r1 = (ks * 8 + tig + 4) * 136;
            uint32_t afh[2][4], afl[2][4], bfh[4][2], bfl[4][2];
#pragma unroll
            for (int mi = 0; mi < 2; mi++) {
                int mc = wm0 + mi * 16 + gid;
                afh[mi][0] = __float_as_uint(AsH[r0 + mc]);
                afh[mi][1] = __float_as_uint(AsH[r0 + mc + 8]);
                afh[mi][2] = __float_as_uint(AsH[r1 + mc]);
                afh[mi][3] = __float_as_uint(AsH[r1 + mc + 8]);
                afl[mi][0] = __float_as_uint(AsL[r0 + mc]);
                afl[mi][1] = __float_as_uint(AsL[r0 + mc + 8]);
                afl[mi][2] = __float_as_uint(AsL[r1 + mc]);
                afl[mi][3] = __float_as_uint(AsL[r1 + mc + 8]);
            }
#pragma unroll
            for (int j = 0; j < 4; j++) {
                int nc = wn0 + j * 8 + gid;
                bfh[j][0] = __float_as_uint(BsH[r0 + nc]);
                bfh[j][1] = __float_as_uint(BsH[r1 + nc]);
                bfl[j][0] = __float_as_uint(BsL[r0 + nc]);
                bfl[j][1] = __float_as_uint(BsL[r1 + nc]);
            }
#pragma unroll
            for (int mi = 0; mi < 2; mi++)
#pragma unroll
                for (int j = 0; j < 4; j++) {
                    mma_tf32(acc[mi][j], afl[mi], bfh[j]);   // lo*hi
                    mma_tf32(acc[mi][j], afh[mi], bfl[j]);   // hi*lo
                    mma_tf32(acc[mi][j], afh[mi], bfh[j]);   // hi*hi
                }
        }
        __syncthreads();
        if (kb < 7) {
            STORE_TILES();
            __syncthreads();
        }
    }
#undef STORE_TILES

    const float sc = 0.08838834764831845f;       // 1/sqrt(128)

    if constexpr (!FUSE) {
        // coarse: write scaled correlation to g_cc
        float* out = g_cc + (size_t)b * MT * MT;
        (void)outC; (void)outF;
#pragma unroll
        for (int mi = 0; mi < 2; mi++)
#pragma unroll
            for (int j = 0; j < 4; j++) {
                int r0 = m0 + wm0 + mi * 16 + gid;
                int cc = n0 + wn0 + j * 8 + 2 * tig;
                float2 v0 = make_float2(acc[mi][j][0] * sc, acc[mi][j][1] * sc);
                float2 v1 = make_float2(acc[mi][j][2] * sc, acc[mi][j][3] * sc);
                *reinterpret_cast<float2*>(&out[(size_t)r0 * MT + cc])       = v0;
                *reinterpret_cast<float2*>(&out[(size_t)(r0 + 8) * MT + cc]) = v1;
            }
    } else {
        // fine: c = 0.5*(rowinterp + corr), plus transposed write for c_flip
        float* S = smem;                          // 128 x 65 (33.3 KB)
        float* Y = smem + 8320;                   // 64 x 68  (17.4 KB): y-blended g_i1
        const size_t cb = (size_t)b * MT * MT;
        const int h0base = m0 >> 6;               // two h0 values: h0base, h0base+1

#pragma unroll
        for (int ch = 0; ch < 2; ch++) {
            const int nbase = n0 + ch * 64;

            // --- store this half's corr into S (warps with wn0 in this half) ---
            if (((warp >> 1) & 1) == ch) {
                const int colbase = (warp & 1) * 32;
#pragma unroll
                for (int mi = 0; mi < 2; mi++)
#pragma unroll
                    for (int j = 0; j < 4; j++) {
                        int r0  = wm0 + mi * 16 + gid;
                        int col = colbase + j * 8 + 2 * tig;
                        S[r0 * 65 + col]           = acc[mi][j][0] * sc;
                        S[r0 * 65 + col + 1]       = acc[mi][j][1] * sc;
                        S[(r0 + 8) * 65 + col]     = acc[mi][j][2] * sc;
                        S[(r0 + 8) * 65 + col + 1] = acc[mi][j][3] * sc;
                    }
            }

            // --- build Y: y-blend of g_i1 rows for the 2 h0 values, 32 cx, 64 cols ---
#pragma unroll
            for (int t = 0; t < 2; t++) {
                int e     = tid + t * 512;
                int h0loc = e >> 9;
                int cx    = (e >> 4) & 31;
                int c4    = e & 15;
                int y0, y1; float wy;
                lerp_weights(h0base + h0loc, y0, y1, wy);
                const float4* p0 = reinterpret_cast<const float4*>(
                    g_i1 + ((size_t)b * 1024 + y0 * 32 + cx) * 4096 + nbase) + c4;
                const float4* p1 = reinterpret_cast<const float4*>(
                    g_i1 + ((size_t)b * 1024 + y1 * 32 + cx) * 4096 + nbase) + c4;
                float4 a = *p0, bb = *p1;
                float4 v;
                v.x = a.x + wy * (bb.x - a.x);
                v.y = a.y + wy * (bb.y - a.y);
                v.z = a.z + wy * (bb.z - a.z);
                v.w = a.w + wy * (bb.w - a.w);
                *reinterpret_cast<float4*>(&Y[(h0loc * 32 + cx) * 68 + c4 * 4]) = v;
            }
            __syncthreads();

            // --- combine: x-blend + corr, write c, keep combined in S ---
#pragma unroll
            for (int q = 0; q < 4; q++) {
                int idx = tid + q * 512;          // float4 units over 128x64
                int r   = idx >> 4;
                int cf  = (idx & 15) << 2;
                int h0loc = r >> 6;
                int w0    = r & 63;
                int x0, x1; float wx;
                lerp_weights(w0, x0, x1, wx);
                float4 ya = *reinterpret_cast<const float4*>(&Y[(h0loc * 32 + x0) * 68 + cf]);
                float4 yb = *reinterpret_cast<const float4*>(&Y[(h0loc * 32 + x1) * 68 + cf]);
                float4 ip;
                ip.x = ya.x + wx * (yb.x - ya.x);
                ip.y = ya.y + wx * (yb.y - ya.y);
                ip.z = ya.z + wx * (yb.z - ya.z);
                ip.w = ya.w + wx * (yb.w - ya.w);
                size_t ga = cb + (size_t)(m0 + r) * MT + nbase + cf;
                float4 v;
                v.x = 0.5f * (ip.x + S[r * 65 + cf]);
                v.y = 0.5f * (ip.y + S[r * 65 + cf + 1]);
                v.z = 0.5f * (ip.z + S[r * 65 + cf + 2]);
                v.w = 0.5f * (ip.w + S[r * 65 + cf + 3]);
                *reinterpret_cast<float4*>(outC + ga) = v;
                S[r * 65 + cf]     = v.x;         // keep combined value for flip write
                S[r * 65 + cf + 1] = v.y;
                S[r * 65 + cf + 2] = v.z;
                S[r * 65 + cf + 3] = v.w;
            }
            __syncthreads();

            // --- transposed rows: c_flip[n][m0..m0+127] ---
#pragma unroll
            for (int jr = 0; jr < 4; jr++) {
                int n = warp * 4 + jr;
                size_t fb = cb + (size_t)(nbase + n) * MT + m0;
#pragma unroll
                for (int q = 0; q < 4; q++) {
                    int m = lane + q * 32;        // bank = (m+n)%32 -> conflict-free
                    outF[fb + m] = S[m * 65 + n];
                }
            }
            __syncthreads();
        }
    }
}

// ---------------------------------------------------------------------------
// trans_features_coarse: bilinear 32->64 (align_corners) per channel
// ---------------------------------------------------------------------------
__global__ __launch_bounds__(256)
void resize_coarse_kernel(const float* __restrict__ a, const float* __restrict__ bsrc,
                          float* __restrict__ out)
{
    __shared__ float s[1024];
    int blk = blockIdx.x;                        // 0..511
    int bb = blk >> 8, ii = (blk >> 7) & 1, ch = blk & 127;
    const float* in = (ii ? bsrc : a) + ((size_t)bb * 128 + ch) * 1024;
    float* o = out + (((size_t)bb * 2 + ii) * 128 + ch) * 4096;
    int tid = threadIdx.x;
#pragma unroll
    for (int q = 0; q < 4; q++) s[tid + q * 256] = in[tid + q * 256];
    __syncthreads();
#pragma unroll
    for (int q = 0; q < 16; q++) {
        int oi = tid + q * 256;
        int oy = oi >> 6, ox = oi & 63;
        int y0, y1, x0, x1; float wy, wx;
        lerp_weights(oy, y0, y1, wy);
        lerp_weights(ox, x0, x1, wx);
        float v = (1.0f - wy) * ((1.0f - wx) * s[y0 * 32 + x0] + wx * s[y0 * 32 + x1])
                +         wy  * ((1.0f - wx) * s[y1 * 32 + x0] + wx * s[y1 * 32 + x1]);
        o[oi] = v;
    }
}

// ---------------------------------------------------------------------------
// interp pass A: per (b,p0c) row, upsample (u,v) 32x32 -> 64x64
// ---------------------------------------------------------------------------
__global__ __launch_bounds__(256)
void interpA_kernel()
{
    __shared__ float s[1024];
    int blk = blockIdx.x;                        // 0..2047 = b*1024 + p0c
    const float* in = g_cc + (size_t)blk * 1024;
    float* o = g_i1 + (size_t)blk * 4096;
    int tid = threadIdx.x;
#pragma unroll
    for (int q = 0; q < 4; q++) s[tid + q * 256] = in[tid + q * 256];
    __syncthreads();
#pragma unroll
    for (int q = 0; q < 16; q++) {
        int oi = tid + q * 256;
        int oy = oi >> 6, ox = oi & 63;
        int y0, y1, x0, x1; float wy, wx;
        lerp_weights(oy, y0, y1, wy);
        lerp_weights(ox, x0, x1, wx);
        float v = (1.0f - wy) * ((1.0f - wx) * s[y0 * 32 + x0] + wx * s[y0 * 32 + x1])
                +         wy  * ((1.0f - wx) * s[y1 * 32 + x0] + wx * s[y1 * 32 + x1]);
        o[oi] = v;
    }
}

// ---------------------------------------------------------------------------
// soft-argmax: softmax(row/0.02) over 4096 source positions, marginal means.
// One block per (target pixel, batch); z selects (c -> flow) / (c_flip -> flow_flip).
// ---------------------------------------------------------------------------
__global__ __launch_bounds__(256)
void softargmax_kernel(const float* __restrict__ c0, const float* __restrict__ c1,
                       float* __restrict__ fl0, float* __restrict__ fl1)
{
    const int t  = blockIdx.x;
    const int bb = blockIdx.y;
    const float* cmat = blockIdx.z ? c1 : c0;
    float* flow       = blockIdx.z ? fl1 : fl0;
    const float* row = cmat + ((size_t)bb * 4096 + t) * 4096;
    const int tid = threadIdx.x;
    const int warp = tid >> 5, lane = tid & 31;

    float v[16];
    const float4* r4 = reinterpret_cast<const float4*>(row) + tid * 4;
#pragma unroll
    for (int q = 0; q < 4; q++) {
        float4 x = r4[q];
        v[q * 4] = x.x; v[q * 4 + 1] = x.y; v[q * 4 + 2] = x.z; v[q * 4 + 3] = x.w;
    }

    float mx = v[0];
#pragma unroll
    for (int e = 1; e < 16; e++) mx = fmaxf(mx, v[e]);
#pragma unroll
    for (int o = 16; o; o >>= 1) mx = fmaxf(mx, __shfl_xor_sync(0xffffffffu, mx, o));

    __shared__ float smax[8];
    if (lane == 0) smax[warp] = mx;
    __syncthreads();
    mx = smax[0];
#pragma unroll
    for (int i = 1; i < 8; i++) mx = fmaxf(mx, smax[i]);

    float Z = 0.0f, Sx = 0.0f, Sy = 0.0f;
    const int base = tid * 16;
#pragma unroll
    for (int e = 0; e < 16; e++) {
        float tt = (v[e] - mx) * 50.0f;           // /beta = *50
        if (tt > -25.0f) {                        // skipped terms < 1.4e-11 * Z
            float ee = __expf(tt);
            int idx = base + e;
            float xn = (float)((idx & 63) * 2) / 63.0f - 1.0f;
            float yn = (float)((idx >> 6) * 2) / 63.0f - 1.0f;
            Z += ee; Sx += ee * xn; Sy += ee * yn;
        }
    }
#pragma unroll
    for (int o = 16; o; o >>= 1) {
        Z  += __shfl_xor_sync(0xffffffffu, Z,  o);
        Sx += __shfl_xor_sync(0xffffffffu, Sx, o);
        Sy += __shfl_xor_sync(0xffffffffu, Sy, o);
    }
    __shared__ float sz[8], sxs[8], sys[8];
    if (lane == 0) { sz[warp] = Z; sxs[warp] = Sx; sys[warp] = Sy; }
    __syncthreads();
    if (tid == 0) {
        float z = 0.0f, X = 0.0f, Y = 0.0f;
#pragma unroll
        for (int i = 0; i < 8; i++) { z += sz[i]; X += sxs[i]; Y += sys[i]; }
        float gx = X / z, gy = Y / z;
        float w = (float)(t & 63), h = (float)(t >> 6);
        flow[(size_t)bb * 2 * 4096 + t]        = (gx + 1.0f) * 31.5f - w;
        flow[(size_t)bb * 2 * 4096 + 4096 + t] = (gy + 1.0f) * 31.5f - h;
    }
}

// ---------------------------------------------------------------------------
// launch
// ---------------------------------------------------------------------------
extern "C" void kernel_launch(void* const* d_in, const int* in_sizes, int n_in,
                              void* d_out, int out_size)
{
    (void)in_sizes; (void)n_in; (void)out_size;
    const float* f0c = (const float*)d_in[0];
    const float* f1c = (const float*)d_in[1];
    const float* f0f = (const float*)d_in[2];
    const float* f1f = (const float*)d_in[3];
    float* out = (float*)d_out;

    cudaFuncSetAttribute(gemm_corr_kernel<4096, true>,
                         cudaFuncAttributeMaxDynamicSharedMemorySize, 50688);

    // trans_features = stack([feat0_f, feat1_f], axis=1): [b][i][C*64*64]
    const size_t chunk = (size_t)128 * 4096;      // floats per (b,i)
    cudaMemcpyAsync(out + OFF_TF + 0 * chunk, f0f,         chunk * 4, cudaMemcpyDeviceToDevice, 0);
    cudaMemcpyAsync(out + OFF_TF + 1 * chunk, f1f,         chunk * 4, cudaMemcpyDeviceToDevice, 0);
    cudaMemcpyAsync(out + OFF_TF + 2 * chunk, f0f + chunk, chunk * 4, cudaMemcpyDeviceToDevice, 0);
    cudaMemcpyAsync(out + OFF_TF + 3 * chunk, f1f + chunk, chunk * 4, cudaMemcpyDeviceToDevice, 0);

    resize_coarse_kernel<<<512, 256>>>(f0c, f1c, out + OFF_TFC);

    gemm_corr_kernel<1024, false><<<dim3(8, 8, 2), 512, 34816>>>(f0c, f1c, nullptr, nullptr);
    interpA_kernel<<<2048, 256>>>();
    gemm_corr_kernel<4096, true><<<dim3(32, 32, 2), 512, 50688>>>(f0f, f1f, out + OFF_C, out + OFF_CF);

    softargmax_kernel<<<dim3(4096, 2, 2), 256>>>(out + OFF_C, out + OFF_CF,
                                                 out + OFF_FLOW, out + OFF_FLOWF);
}

// round 5
// speedup vs baseline: 1.3639x; 1.2150x over previous
#include <cuda_runtime.h>
#include <cstdint>

// ---------------------------------------------------------------------------
// Problem constants
//   feat0_c, feat1_c : [2,128,32,32] fp32
//   feat0_f, feat1_f : [2,128,64,64] fp32
// ---------------------------------------------------------------------------

static const size_t OFF_TF    = 0;
static const size_t OFF_TFC   = 2097152;
static const size_t OFF_C     = 4194304;
static const size_t OFF_CF    = 37748736;
static const size_t OFF_FLOW  = 71303168;
static const size_t OFF_FLOWF = 71319552;

// Scratch (device globals — no allocation allowed)
__device__ float g_cc[2 * 1024 * 1024];          // corr_c  [b][p0c][p1c]   8 MB
__device__ float g_i1[2 * 1024 * 4096];          // (u,v)-upsampled corr_c  33.5 MB (L2-resident)

// ---------------------------------------------------------------------------
// helpers
// ---------------------------------------------------------------------------
__device__ __forceinline__ uint32_t pack_bf16x2(float hi, float lo) {
    // d = { hi -> upper 16, lo -> lower 16 }, round-to-nearest
    uint32_t r;
    asm("cvt.rn.bf16x2.f32 %0, %1, %2;" : "=r"(r) : "f"(hi), "f"(lo));
    return r;
}

__device__ __forceinline__ void mma_bf16(float* d, const uint32_t* a, const uint32_t* b) {
    asm volatile(
        "mma.sync.aligned.m16n8k16.row.col.f32.bf16.bf16.f32 "
        "{%0,%1,%2,%3}, {%4,%5,%6,%7}, {%8,%9}, {%0,%1,%2,%3};\n"
        : "+f"(d[0]), "+f"(d[1]), "+f"(d[2]), "+f"(d[3])
        : "r"(a[0]), "r"(a[1]), "r"(a[2]), "r"(a[3]), "r"(b[0]), "r"(b[1]));
}

__device__ __forceinline__ void lerp_weights(int i, int& i0, int& i1, float& w) {
    float f = (float)(i * 31) / 63.0f;   // align_corners scale 31/63, exact at i=0,63
    i0 = (int)f;
    w  = f - (float)i0;
    i1 = min(i0 + 1, 31);
}

// ---------------------------------------------------------------------------
// Correlation GEMM (bf16x3, near-fp32 accuracy), 512 threads / 16 warps:
//   C[m,n] = sum_k f0[b,k,m] * f1[b,k,n] * (1/sqrt(128))
// Split x = hi + lo (both bf16, RN); C += hi*hi + hi*lo + lo*hi.
// Block tile 128x128, warp tile 32x32 (4x4 warp grid), BK=16 per chunk,
// mma.m16n8k16. Operands packed 2-k-per-word in smem: [k2][m] uint32,
// row stride 136 words -> fragment LDS bank = 8*tig+gid (conflict-free).
// Register-prefetch pipeline across the 8 k-chunks.
// FUSE epilogue: c = 0.5*(rowinterp(g_i1) + corr), writes c + c_flip.
// ---------------------------------------------------------------------------
template <int MT, bool FUSE>
__global__ __launch_bounds__(512)
void gemm_corr_kernel(const float* __restrict__ f0, const float* __restrict__ f1,
                      float* __restrict__ outC, float* __restrict__ outF)
{
    extern __shared__ uint32_t smemw[];
    uint32_t* AsH = smemw;               // 8 x 136 words
    uint32_t* AsL = smemw + 1088;
    uint32_t* BsH = smemw + 2176;
    uint32_t* BsL = smemw + 3264;

    const int b  = blockIdx.z;
    const int m0 = blockIdx.y * 128;
    const int n0 = blockIdx.x * 128;
    const float* A  = f0 + (size_t)b * 128 * MT;  // [K=128][MT]
    const float* Bg = f1 + (size_t)b * 128 * MT;

    const int tid  = threadIdx.x;
    const int warp = tid >> 5, lane = tid & 31;
    const int gid  = lane >> 2, tig = lane & 3;
    const int wm0  = (warp >> 2) * 32;           // 4 warp rows
    const int wn0  = (warp & 3) * 32;            // 4 warp cols

    float acc[2][4][4];
#pragma unroll
    for (int mi = 0; mi < 2; mi++)
#pragma unroll
        for (int j = 0; j < 4; j++)
#pragma unroll
            for (int r = 0; r < 4; r++) acc[mi][j][r] = 0.0f;

    // loader: thread handles one k-pair (k2) x two m columns
    const int lk2 = tid >> 6;            // 0..7
    const int lmp = (tid & 63) << 1;     // 0..126 step 2

    float2 pa0, pa1, pb0, pb1;
#define LOAD_CHUNK(kb)                                                              \
    do {                                                                            \
        const float* Ar = A  + (size_t)((kb) * 16 + 2 * lk2) * MT + m0 + lmp;       \
        const float* Br = Bg + (size_t)((kb) * 16 + 2 * lk2) * MT + n0 + lmp;       \
        pa0 = *reinterpret_cast<const float2*>(Ar);                                 \
        pa1 = *reinterpret_cast<const float2*>(Ar + MT);                            \
        pb0 = *reinterpret_cast<const float2*>(Br);                                 \
        pb1 = *reinterpret_cast<const float2*>(Br + MT);                            \
    } while (0)

#define STORE_CHUNK()                                                               \
    do {                                                                            \
        uint32_t ah0 = pack_bf16x2(pa1.x, pa0.x);   /* m+0: (k1,k0) */              \
        uint32_t ah1 = pack_bf16x2(pa1.y, pa0.y);   /* m+1 */                       \
        uint32_t bh0 = pack_bf16x2(pb1.x, pb0.x);                                   \
        uint32_t bh1 = pack_bf16x2(pb1.y, pb0.y);                                   \
        uint32_t al0 = pack_bf16x2(pa1.x - __uint_as_float(ah0 & 0xffff0000u),      \
                                   pa0.x - __uint_as_float(ah0 << 16));             \
        uint32_t al1 = pack_bf16x2(pa1.y - __uint_as_float(ah1 & 0xffff0000u),      \
                                   pa0.y - __uint_as_float(ah1 << 16));             \
        uint32_t bl0 = pack_bf16x2(pb1.x - __uint_as_float(bh0 & 0xffff0000u),      \
                                   pb0.x - __uint_as_float(bh0 << 16));             \
        uint32_t bl1 = pack_bf16x2(pb1.y - __uint_as_float(bh1 & 0xffff0000u),      \
                                   pb0.y - __uint_as_float(bh1 << 16));             \
        *reinterpret_cast<uint2*>(&AsH[lk2 * 136 + lmp]) = make_uint2(ah0, ah1);    \
        *reinterpret_cast<uint2*>(&AsL[lk2 * 136 + lmp]) = make_uint2(al0, al1);    \
        *reinterpret_cast<uint2*>(&BsH[lk2 * 136 + lmp]) = make_uint2(bh0, bh1);    \
        *reinterpret_cast<uint2*>(&BsL[lk2 * 136 + lmp]) = make_uint2(bl0, bl1);    \
    } while (0)

    LOAD_CHUNK(0);
    STORE_CHUNK();
    __syncthreads();

    for (int kb = 0; kb < 8; kb++) {
        if (kb < 7) LOAD_CHUNK(kb + 1);   // prefetch (hidden behind MMA)

        const int r0 = tig * 136;
        const int r1 = (tig + 4) * 136;
        uint32_t afh[2][4], afl[2][4], bfh[4][2], bfl[4][2];
#pragma unroll
        for (int mi = 0; mi < 2; mi++) {
            int mc = wm0 + mi * 16 + gid;
            afh[mi][0] = AsH[r0 + mc];
            afh[mi][1] = AsH[r0 + mc + 8];
            afh[mi][2] = AsH[r1 + mc];
            afh[mi][3] = AsH[r1 + mc + 8];
            afl[mi][0] = AsL[r0 + mc];
            afl[mi][1] = AsL[r0 + mc + 8];
            afl[mi][2] = AsL[r1 + mc];
            afl[mi][3] = AsL[r1 + mc + 8];
        }
#pragma unroll
        for (int j = 0; j < 4; j++) {
            int nc = wn0 + j * 8 + gid;
            bfh[j][0] = BsH[r0 + nc];
            bfh[j][1] = BsH[r1 + nc];
            bfl[j][0] = BsL[r0 + nc];
            bfl[j][1] = BsL[r1 + nc];
        }
#pragma unroll
        for (int mi = 0; mi < 2; mi++)
#pragma unroll
            for (int j = 0; j < 4; j++) {
                mma_bf16(acc[mi][j], afl[mi], bfh[j]);   // lo*hi
                mma_bf16(acc[mi][j], afh[mi], bfl[j]);   // hi*lo
                mma_bf16(acc[mi][j], afh[mi], bfh[j]);   // hi*hi
            }
        __syncthreads();
        if (kb < 7) {
            STORE_CHUNK();
            __syncthreads();
        }
    }
#undef LOAD_CHUNK
#undef STORE_CHUNK

    const float sc = 0.08838834764831845f;       // 1/sqrt(128)

    if constexpr (!FUSE) {
        // coarse: write scaled correlation to g_cc
        float* out = g_cc + (size_t)b * MT * MT;
        (void)outC; (void)outF;
#pragma unroll
        for (int mi = 0; mi < 2; mi++)
#pragma unroll
            for (int j = 0; j < 4; j++) {
                int r0 = m0 + wm0 + mi * 16 + gid;
                int cc = n0 + wn0 + j * 8 + 2 * tig;
                float2 v0 = make_float2(acc[mi][j][0] * sc, acc[mi][j][1] * sc);
                float2 v1 = make_float2(acc[mi][j][2] * sc, acc[mi][j][3] * sc);
                *reinterpret_cast<float2*>(&out[(size_t)r0 * MT + cc])       = v0;
                *reinterpret_cast<float2*>(&out[(size_t)(r0 + 8) * MT + cc]) = v1;
            }
    } else {
        // fine: c = 0.5*(rowinterp + corr), plus transposed write for c_flip
        float* S = reinterpret_cast<float*>(smemw);        // 128 x 65 (33.3 KB)
        float* Y = reinterpret_cast<float*>(smemw) + 8320; // 64 x 68  (17.4 KB)
        const size_t cb = (size_t)b * MT * MT;
        const int h0base = m0 >> 6;               // two h0 values: h0base, h0base+1

#pragma unroll
        for (int ch = 0; ch < 2; ch++) {
            const int nbase = n0 + ch * 64;

            // --- store this half's corr into S (warps with wn0 in this half) ---
            if (((warp >> 1) & 1) == ch) {
                const int colbase = (warp & 1) * 32;
#pragma unroll
                for (int mi = 0; mi < 2; mi++)
#pragma unroll
                    for (int j = 0; j < 4; j++) {
                        int r0  = wm0 + mi * 16 + gid;
                        int col = colbase + j * 8 + 2 * tig;
                        S[r0 * 65 + col]           = acc[mi][j][0] * sc;
                        S[r0 * 65 + col + 1]       = acc[mi][j][1] * sc;
                        S[(r0 + 8) * 65 + col]     = acc[mi][j][2] * sc;
                        S[(r0 + 8) * 65 + col + 1] = acc[mi][j][3] * sc;
                    }
            }

            // --- build Y: y-blend of g_i1 rows for the 2 h0 values, 32 cx, 64 cols ---
#pragma unroll
            for (int t = 0; t < 2; t++) {
                int e     = tid + t * 512;
                int h0loc = e >> 9;
                int cx    = (e >> 4) & 31;
                int c4    = e & 15;
                int y0, y1; float wy;
                lerp_weights(h0base + h0loc, y0, y1, wy);
                const float4* p0 = reinterpret_cast<const float4*>(
                    g_i1 + ((size_t)b * 1024 + y0 * 32 + cx) * 4096 + nbase) + c4;
                const float4* p1 = reinterpret_cast<const float4*>(
                    g_i1 + ((size_t)b * 1024 + y1 * 32 + cx) * 4096 + nbase) + c4;
                float4 a = *p0, bb = *p1;
                float4 v;
                v.x = a.x + wy * (bb.x - a.x);
                v.y = a.y + wy * (bb.y - a.y);
                v.z = a.z + wy * (bb.z - a.z);
                v.w = a.w + wy * (bb.w - a.w);
                *reinterpret_cast<float4*>(&Y[(h0loc * 32 + cx) * 68 + c4 * 4]) = v;
            }
            __syncthreads();

            // --- combine: x-blend + corr, write c, keep combined in S ---
#pragma unroll
            for (int q = 0; q < 4; q++) {
                int idx = tid + q * 512;          // float4 units over 128x64
                int r   = idx >> 4;
                int cf  = (idx & 15) << 2;
                int h0loc = r >> 6;
                int w0    = r & 63;
                int x0, x1; float wx;
                lerp_weights(w0, x0, x1, wx);
                float4 ya = *reinterpret_cast<const float4*>(&Y[(h0loc * 32 + x0) * 68 + cf]);
                float4 yb = *reinterpret_cast<const float4*>(&Y[(h0loc * 32 + x1) * 68 + cf]);
                float4 ip;
                ip.x = ya.x + wx * (yb.x - ya.x);
                ip.y = ya.y + wx * (yb.y - ya.y);
                ip.z = ya.z + wx * (yb.z - ya.z);
                ip.w = ya.w + wx * (yb.w - ya.w);
                size_t ga = cb + (size_t)(m0 + r) * MT + nbase + cf;
                float4 v;
                v.x = 0.5f * (ip.x + S[r * 65 + cf]);
                v.y = 0.5f * (ip.y + S[r * 65 + cf + 1]);
                v.z = 0.5f * (ip.z + S[r * 65 + cf + 2]);
                v.w = 0.5f * (ip.w + S[r * 65 + cf + 3]);
                *reinterpret_cast<float4*>(outC + ga) = v;
                S[r * 65 + cf]     = v.x;         // keep combined value for flip write
                S[r * 65 + cf + 1] = v.y;
                S[r * 65 + cf + 2] = v.z;
                S[r * 65 + cf + 3] = v.w;
            }
            __syncthreads();

            // --- transposed rows: c_flip[n][m0..m0+127] ---
#pragma unroll
            for (int jr = 0; jr < 4; jr++) {
                int n = warp * 4 + jr;
                size_t fb = cb + (size_t)(nbase + n) * MT + m0;
#pragma unroll
                for (int q = 0; q < 4; q++) {
                    int m = lane + q * 32;        // bank = (m+n)%32 -> conflict-free
                    outF[fb + m] = S[m * 65 + n];
                }
            }
            __syncthreads();
        }
    }
}

// ---------------------------------------------------------------------------
// trans_features_coarse: bilinear 32->64 (align_corners) per channel
// ---------------------------------------------------------------------------
__global__ __launch_bounds__(256)
void resize_coarse_kernel(const float* __restrict__ a, const float* __restrict__ bsrc,
                          float* __restrict__ out)
{
    __shared__ float s[1024];
    int blk = blockIdx.x;                        // 0..511
    int bb = blk >> 8, ii = (blk >> 7) & 1, ch = blk & 127;
    const float* in = (ii ? bsrc : a) + ((size_t)bb * 128 + ch) * 1024;
    float* o = out + (((size_t)bb * 2 + ii) * 128 + ch) * 4096;
    int tid = threadIdx.x;
#pragma unroll
    for (int q = 0; q < 4; q++) s[tid + q * 256] = in[tid + q * 256];
    __syncthreads();
#pragma unroll
    for (int q = 0; q < 16; q++) {
        int oi = tid + q * 256;
        int oy = oi >> 6, ox = oi & 63;
        int y0, y1, x0, x1; float wy, wx;
        lerp_weights(oy, y0, y1, wy);
        lerp_weights(ox, x0, x1, wx);
        float v = (1.0f - wy) * ((1.0f - wx) * s[y0 * 32 + x0] + wx * s[y0 * 32 + x1])
                +         wy  * ((1.0f - wx) * s[y1 * 32 + x0] + wx * s[y1 * 32 + x1]);
        o[oi] = v;
    }
}

// ---------------------------------------------------------------------------
// interp pass A: per (b,p0c) row, upsample (u,v) 32x32 -> 64x64
// ---------------------------------------------------------------------------
__global__ __launch_bounds__(256)
void interpA_kernel()
{
    __shared__ float s[1024];
    int blk = blockIdx.x;                        // 0..2047 = b*1024 + p0c
    const float* in = g_cc + (size_t)blk * 1024;
    float* o = g_i1 + (size_t)blk * 4096;
    int tid = threadIdx.x;
#pragma unroll
    for (int q = 0; q < 4; q++) s[tid + q * 256] = in[tid + q * 256];
    __syncthreads();
#pragma unroll
    for (int q = 0; q < 16; q++) {
        int oi = tid + q * 256;
        int oy = oi >> 6, ox = oi & 63;
        int y0, y1, x0, x1; float wy, wx;
        lerp_weights(oy, y0, y1, wy);
        lerp_weights(ox, x0, x1, wx);
        float v = (1.0f - wy) * ((1.0f - wx) * s[y0 * 32 + x0] + wx * s[y0 * 32 + x1])
                +         wy  * ((1.0f - wx) * s[y1 * 32 + x0] + wx * s[y1 * 32 + x1]);
        o[oi] = v;
    }
}

// ---------------------------------------------------------------------------
// soft-argmax: softmax(row/0.02) over 4096 source positions, marginal means.
// One block per (target pixel, batch); z selects (c -> flow) / (c_flip -> flow_flip).
// ---------------------------------------------------------------------------
__global__ __launch_bounds__(256)
void softargmax_kernel(const float* __restrict__ c0, const float* __restrict__ c1,
                       float* __restrict__ fl0, float* __restrict__ fl1)
{
    const int t  = blockIdx.x;
    const int bb = blockIdx.y;
    const float* cmat = blockIdx.z ? c1 : c0;
    float* flow       = blockIdx.z ? fl1 : fl0;
    const float* row = cmat + ((size_t)bb * 4096 + t) * 4096;
    const int tid = threadIdx.x;
    const int warp = tid >> 5, lane = tid & 31;

    float v[16];
    const float4* r4 = reinterpret_cast<const float4*>(row) + tid * 4;
#pragma unroll
    for (int q = 0; q < 4; q++) {
        float4 x = r4[q];
        v[q * 4] = x.x; v[q * 4 + 1] = x.y; v[q * 4 + 2] = x.z; v[q * 4 + 3] = x.w;
    }

    float mx = v[0];
#pragma unroll
    for (int e = 1; e < 16; e++) mx = fmaxf(mx, v[e]);
#pragma unroll
    for (int o = 16; o; o >>= 1) mx = fmaxf(mx, __shfl_xor_sync(0xffffffffu, mx, o));

    __shared__ float smax[8];
    if (lane == 0) smax[warp] = mx;
    __syncthreads();
    mx = smax[0];
#pragma unroll
    for (int i = 1; i < 8; i++) mx = fmaxf(mx, smax[i]);

    float Z = 0.0f, Sx = 0.0f, Sy = 0.0f;
    const int base = tid * 16;
#pragma unroll
    for (int e = 0; e < 16; e++) {
        float tt = (v[e] - mx) * 50.0f;           // /beta = *50
        if (tt > -25.0f) {                        // skipped terms < 1.4e-11 * Z
            float ee = __expf(tt);
            int idx = base + e;
            float xn = (float)((idx & 63) * 2) / 63.0f - 1.0f;
            float yn = (float)((idx >> 6) * 2) / 63.0f - 1.0f;
            Z += ee; Sx += ee * xn; Sy += ee * yn;
        }
    }
#pragma unroll
    for (int o = 16; o; o >>= 1) {
        Z  += __shfl_xor_sync(0xffffffffu, Z,  o);
        Sx += __shfl_xor_sync(0xffffffffu, Sx, o);
        Sy += __shfl_xor_sync(0xffffffffu, Sy, o);
    }
    __shared__ float sz[8], sxs[8], sys[8];
    if (lane == 0) { sz[warp] = Z; sxs[warp] = Sx; sys[warp] = Sy; }
    __syncthreads();
    if (tid == 0) {
        float z = 0.0f, X = 0.0f, Y = 0.0f;
#pragma unroll
        for (int i = 0; i < 8; i++) { z += sz[i]; X += sxs[i]; Y += sys[i]; }
        float gx = X / z, gy = Y / z;
        float w = (float)(t & 63), h = (float)(t >> 6);
        flow[(size_t)bb * 2 * 4096 + t]        = (gx + 1.0f) * 31.5f - w;
        flow[(size_t)bb * 2 * 4096 + 4096 + t] = (gy + 1.0f) * 31.5f - h;
    }
}

// ---------------------------------------------------------------------------
// launch
// ---------------------------------------------------------------------------
extern "C" void kernel_launch(void* const* d_in, const int* in_sizes, int n_in,
                              void* d_out, int out_size)
{
    (void)in_sizes; (void)n_in; (void)out_size;
    const float* f0c = (const float*)d_in[0];
    const float* f1c = (const float*)d_in[1];
    const float* f0f = (const float*)d_in[2];
    const float* f1f = (const float*)d_in[3];
    float* out = (float*)d_out;

    cudaFuncSetAttribute(gemm_corr_kernel<4096, true>,
                         cudaFuncAttributeMaxDynamicSharedMemorySize, 50688);

    // trans_features = stack([feat0_f, feat1_f], axis=1): [b][i][C*64*64]
    const size_t chunk = (size_t)128 * 4096;      // floats per (b,i)
    cudaMemcpyAsync(out + OFF_TF + 0 * chunk, f0f,         chunk * 4, cudaMemcpyDeviceToDevice, 0);
    cudaMemcpyAsync(out + OFF_TF + 1 * chunk, f1f,         chunk * 4, cudaMemcpyDeviceToDevice, 0);
    cudaMemcpyAsync(out + OFF_TF + 2 * chunk, f0f + chunk, chunk * 4, cudaMemcpyDeviceToDevice, 0);
    cudaMemcpyAsync(out + OFF_TF + 3 * chunk, f1f + chunk, chunk * 4, cudaMemcpyDeviceToDevice, 0);

    resize_coarse_kernel<<<512, 256>>>(f0c, f1c, out + OFF_TFC);

    gemm_corr_kernel<1024, false><<<dim3(8, 8, 2), 512, 17408>>>(f0c, f1c, nullptr, nullptr);
    interpA_kernel<<<2048, 256>>>();
    gemm_corr_kernel<4096, true><<<dim3(32, 32, 2), 512, 50688>>>(f0f, f1f, out + OFF_C, out + OFF_CF);

    softargmax_kernel<<<dim3(4096, 2, 2), 256>>>(out + OFF_C, out + OFF_CF,
                                                 out + OFF_FLOW, out + OFF_FLOWF);
}